// round 1
// baseline (speedup 1.0000x reference)
#include <cuda_runtime.h>

#define NMP     3
#define NNODES  50000
#define D       128
#define E       32
#define DEG     32
#define NEDGE   200000
#define BB      1024
#define S       16
#define NC      8
#define M1      (BB*S)      /* 16384 */
#define DE      (D+E)       /* 160 */

// ---------------- scratch (static device globals; no runtime alloc) ----------------
__device__ int   g_nb1 [NMP*M1];
__device__ int   g_eid1[NMP*M1];
__device__ float g_nin2[(size_t)NMP*M1*DE];   // hop-2 mean [3,16384,160]
__device__ float g_nin1[NMP*BB*DE];           // hop-1 mean [3,1024,160]
__device__ float g_h1  [(size_t)NMP*M1*D];    // layer0 feats at hop-1 [3,16384,128]
__device__ float g_h0  [NMP*BB*D];            // layer0 feats at root  [3,1024,128]
__device__ float g_e1  [(size_t)NMP*M1*E];    // layer0 updated edges  [3,16384,32]
__device__ float g_ninL1[NMP*BB*DE];          // layer1 mean [3,1024,160]
__device__ float g_outs[NMP*BB*D];            // per-metapath embedding [3,1024,128]

// ---------------- 1) hop-1 neighbor / edge ids ----------------
__global__ void k_idx(const int* __restrict__ ids,
                      const int* __restrict__ adj_nodes,
                      const int* __restrict__ adj_edges) {
    int t = blockIdx.x * blockDim.x + threadIdx.x;
    if (t >= NMP * M1) return;
    int mp = t / M1;
    int r  = t % M1;
    int b  = r >> 4;
    int s  = r & 15;
    long base = ((long)mp * NNODES + ids[b]) * DEG + s;
    g_nb1[t]  = adj_nodes[base];
    g_eid1[t] = adj_edges[base];
}

// ---------------- 2) hop-2 gather + mean -> nin2 ----------------
__global__ void k_mean_hop2(const float* __restrict__ feats,
                            const float* __restrict__ edge_emb,
                            const int* __restrict__ adj_nodes,
                            const int* __restrict__ adj_edges) {
    int w    = (blockIdx.x * blockDim.x + threadIdx.x) >> 5;
    int lane = threadIdx.x & 31;
    if (w >= NMP * M1) return;
    int mp = w / M1;
    long abase = ((long)mp * NNODES + g_nb1[w]) * DEG;
    const int* an = adj_nodes + abase;
    const int* ae = adj_edges + abase;
    float4 aF = make_float4(0.f,0.f,0.f,0.f);
    float4 aE = make_float4(0.f,0.f,0.f,0.f);
    #pragma unroll
    for (int s = 0; s < S; s++) {
        int nb = an[s];
        float4 v = ((const float4*)(feats + (long)nb * D))[lane];
        aF.x += v.x; aF.y += v.y; aF.z += v.z; aF.w += v.w;
        if (lane < E/4) {
            int e = ae[s];
            float4 u = ((const float4*)(edge_emb + ((long)mp * NEDGE + e) * E))[lane];
            aE.x += u.x; aE.y += u.y; aE.z += u.z; aE.w += u.w;
        }
    }
    const float inv = 1.0f / S;
    float4* o = (float4*)(g_nin2 + (size_t)w * DE);
    o[lane] = make_float4(aF.x*inv, aF.y*inv, aF.z*inv, aF.w*inv);
    if (lane < E/4)
        o[D/4 + lane] = make_float4(aE.x*inv, aE.y*inv, aE.z*inv, aE.w*inv);
}

// ---------------- 3) hop-1 gather + mean -> nin1 ----------------
__global__ void k_mean_hop1(const float* __restrict__ feats,
                            const float* __restrict__ edge_emb) {
    int w    = (blockIdx.x * blockDim.x + threadIdx.x) >> 5;
    int lane = threadIdx.x & 31;
    if (w >= NMP * BB) return;
    int mp = w / BB;
    int b  = w % BB;
    int base = mp * M1 + b * S;
    float4 aF = make_float4(0.f,0.f,0.f,0.f);
    float4 aE = make_float4(0.f,0.f,0.f,0.f);
    #pragma unroll
    for (int s = 0; s < S; s++) {
        int nb = g_nb1[base + s];
        float4 v = ((const float4*)(feats + (long)nb * D))[lane];
        aF.x += v.x; aF.y += v.y; aF.z += v.z; aF.w += v.w;
        if (lane < E/4) {
            int e = g_eid1[base + s];
            float4 u = ((const float4*)(edge_emb + ((long)mp * NEDGE + e) * E))[lane];
            aE.x += u.x; aE.y += u.y; aE.z += u.z; aE.w += u.w;
        }
    }
    const float inv = 1.0f / S;
    float4* o = (float4*)(g_nin1 + (size_t)w * DE);
    o[lane] = make_float4(aF.x*inv, aF.y*inv, aF.z*inv, aF.w*inv);
    if (lane < E/4)
        o[D/4 + lane] = make_float4(aE.x*inv, aE.y*inv, aE.z*inv, aE.w*inv);
}

// ---------------- layer-1 mean over (h1 || e1) -> ninL1 ----------------
__global__ void k_mean_L1() {
    int w    = (blockIdx.x * blockDim.x + threadIdx.x) >> 5;
    int lane = threadIdx.x & 31;
    if (w >= NMP * BB) return;
    int mp = w / BB;
    int b  = w % BB;
    size_t base = (size_t)mp * M1 + (size_t)b * S;
    float4 aF = make_float4(0.f,0.f,0.f,0.f);
    float4 aE = make_float4(0.f,0.f,0.f,0.f);
    #pragma unroll
    for (int s = 0; s < S; s++) {
        float4 v = ((const float4*)(g_h1 + (base + s) * D))[lane];
        aF.x += v.x; aF.y += v.y; aF.z += v.z; aF.w += v.w;
        if (lane < E/4) {
            float4 u = ((const float4*)(g_e1 + (base + s) * E))[lane];
            aE.x += u.x; aE.y += u.y; aE.z += u.z; aE.w += u.w;
        }
    }
    const float inv = 1.0f / S;
    float4* o = (float4*)(g_ninL1 + (size_t)w * DE);
    o[lane] = make_float4(aF.x*inv, aF.y*inv, aF.z*inv, aF.w*inv);
    if (lane < E/4)
        o[D/4 + lane] = make_float4(aE.x*inv, aE.y*inv, aE.z*inv, aE.w*inv);
}

// ---------------- node GEMM: out = relu(P1row @ Wself + P2row @ Wneigh) ----------------
// MODE 0: h1  (M=16384, P1 = feats[g_nb1], P2 = nin2)
// MODE 1: h0  (M=1024,  P1 = feats[ids],  P2 = nin1)
// MODE 2: outs(M=1024,  P1 = g_h0 direct, P2 = ninL1)
template<int MODE>
__global__ __launch_bounds__(256) void gemm_h(const float* __restrict__ feats,
                                              const int*   __restrict__ ids,
                                              const float* __restrict__ W_self,
                                              const float* __restrict__ W_neigh,
                                              int l) {
    constexpr int M = (MODE == 0) ? M1 : BB;
    int mp = blockIdx.y;
    int m0 = blockIdx.x * 64;
    __shared__ float As[16][68];      // [k][m], padded (272B rows, 16B aligned)
    __shared__ float Bs[16][132];     // [k][n], padded (528B rows, 16B aligned)
    __shared__ const float* rowp[64];
    int tid = threadIdx.x;

    const float* P2;
    float* Out;
    if (MODE == 0)      { P2 = g_nin2;  Out = g_h1;   }
    else if (MODE == 1) { P2 = g_nin1;  Out = g_h0;   }
    else                { P2 = g_ninL1; Out = g_outs; }

    if (tid < 64) {
        int m = m0 + tid;
        const float* p;
        if (MODE == 0)      p = feats + (long)g_nb1[mp * M1 + m] * D;
        else if (MODE == 1) p = feats + (long)ids[m] * D;
        else                p = g_h0 + ((long)mp * BB + m) * D;
        rowp[tid] = p;
    }
    __syncthreads();

    const float* Wsp = W_self  + ((long)(mp * 2 + l)) * D  * D;
    const float* Wnp = W_neigh + ((long)(mp * 2 + l)) * DE * D;
    const float* P2p = P2 + ((size_t)mp * M + m0) * DE;

    float acc[4][8];
    #pragma unroll
    for (int i = 0; i < 4; i++)
        #pragma unroll
        for (int j = 0; j < 8; j++) acc[i][j] = 0.f;

    int ty = tid >> 4, tx = tid & 15;
    int ar = tid >> 2, kq = (tid & 3) * 4;        // A load: row, k-offset
    int bk = tid >> 4, bn = (tid & 15) * 8;       // B load: k-row, n-offset

    for (int k0 = 0; k0 < D + DE; k0 += 16) {
        float4 av = (k0 < D)
            ? *(const float4*)(rowp[ar] + k0 + kq)
            : *(const float4*)(P2p + (long)ar * DE + (k0 - D) + kq);
        As[kq+0][ar] = av.x; As[kq+1][ar] = av.y;
        As[kq+2][ar] = av.z; As[kq+3][ar] = av.w;

        const float* wrow = (k0 < D) ? (Wsp + (long)(k0 + bk) * D)
                                     : (Wnp + (long)(k0 - D + bk) * D);
        *(float4*)&Bs[bk][bn]     = *(const float4*)(wrow + bn);
        *(float4*)&Bs[bk][bn + 4] = *(const float4*)(wrow + bn + 4);
        __syncthreads();

        #pragma unroll
        for (int k = 0; k < 16; k++) {
            float4 a4 = *(const float4*)&As[k][ty * 4];
            float4 b0 = *(const float4*)&Bs[k][tx * 8];
            float4 b1 = *(const float4*)&Bs[k][tx * 8 + 4];
            float a[4]  = {a4.x, a4.y, a4.z, a4.w};
            float bv[8] = {b0.x, b0.y, b0.z, b0.w, b1.x, b1.y, b1.z, b1.w};
            #pragma unroll
            for (int i = 0; i < 4; i++)
                #pragma unroll
                for (int j = 0; j < 8; j++)
                    acc[i][j] += a[i] * bv[j];
        }
        __syncthreads();
    }

    size_t obase = ((size_t)mp * M + m0) * D;
    #pragma unroll
    for (int i = 0; i < 4; i++) {
        float* orow = Out + obase + (size_t)(ty * 4 + i) * D + tx * 8;
        float4 o0, o1;
        o0.x = fmaxf(acc[i][0], 0.f); o0.y = fmaxf(acc[i][1], 0.f);
        o0.z = fmaxf(acc[i][2], 0.f); o0.w = fmaxf(acc[i][3], 0.f);
        o1.x = fmaxf(acc[i][4], 0.f); o1.y = fmaxf(acc[i][5], 0.f);
        o1.z = fmaxf(acc[i][6], 0.f); o1.w = fmaxf(acc[i][7], 0.f);
        *(float4*)orow       = o0;
        *(float4*)(orow + 4) = o1;
    }
}

// ---------------- edge GEMM: e1 = relu([h0_rep || h1 || ee1] @ W_edge) ----------------
__global__ __launch_bounds__(128) void gemm_edge(const float* __restrict__ edge_emb,
                                                 const float* __restrict__ W_edge,
                                                 int l) {
    int mp = blockIdx.y;
    int m0 = blockIdx.x * 64;
    __shared__ float As[16][68];
    __shared__ float Bs[16][36];
    int tid = threadIdx.x;

    int arl = tid >> 1;
    int m   = m0 + arl;
    int kq  = (tid & 1) * 8;
    const float* pH0 = g_h0 + ((long)mp * BB + (m >> 4)) * D;
    const float* pH1 = g_h1 + ((size_t)mp * M1 + m) * D;
    const float* pE  = edge_emb + ((long)mp * NEDGE + g_eid1[mp * M1 + m]) * E;
    const float* Wep = W_edge + ((long)(mp * 2 + l)) * 288 * E;

    float acc[4][4];
    #pragma unroll
    for (int i = 0; i < 4; i++)
        #pragma unroll
        for (int j = 0; j < 4; j++) acc[i][j] = 0.f;

    int ty = tid >> 3, tx = tid & 7;
    int bk = tid >> 3, bn = (tid & 7) * 4;

    for (int k0 = 0; k0 < 288; k0 += 16) {
        const float* src; int off;
        if (k0 < 128)      { src = pH0; off = k0; }
        else if (k0 < 256) { src = pH1; off = k0 - 128; }
        else               { src = pE;  off = k0 - 256; }
        float4 a0 = *(const float4*)(src + off + kq);
        float4 a1 = *(const float4*)(src + off + kq + 4);
        As[kq+0][arl] = a0.x; As[kq+1][arl] = a0.y;
        As[kq+2][arl] = a0.z; As[kq+3][arl] = a0.w;
        As[kq+4][arl] = a1.x; As[kq+5][arl] = a1.y;
        As[kq+6][arl] = a1.z; As[kq+7][arl] = a1.w;

        *(float4*)&Bs[bk][bn] = *(const float4*)(Wep + (long)(k0 + bk) * E + bn);
        __syncthreads();

        #pragma unroll
        for (int k = 0; k < 16; k++) {
            float4 a4 = *(const float4*)&As[k][ty * 4];
            float4 b4 = *(const float4*)&Bs[k][tx * 4];
            float a[4]  = {a4.x, a4.y, a4.z, a4.w};
            float bv[4] = {b4.x, b4.y, b4.z, b4.w};
            #pragma unroll
            for (int i = 0; i < 4; i++)
                #pragma unroll
                for (int j = 0; j < 4; j++)
                    acc[i][j] += a[i] * bv[j];
        }
        __syncthreads();
    }

    size_t obase = ((size_t)mp * M1 + m0) * E;
    #pragma unroll
    for (int i = 0; i < 4; i++) {
        float* orow = g_e1 + obase + (size_t)(ty * 4 + i) * E + tx * 4;
        float4 o;
        o.x = fmaxf(acc[i][0], 0.f); o.y = fmaxf(acc[i][1], 0.f);
        o.z = fmaxf(acc[i][2], 0.f); o.w = fmaxf(acc[i][3], 0.f);
        *(float4*)orow = o;
    }
}

// ---------------- final fuse: attention + normalize + fc ----------------
__device__ __forceinline__ float blk_red(float v, float* sh) {
    #pragma unroll
    for (int o = 16; o; o >>= 1) v += __shfl_xor_sync(0xffffffffu, v, o);
    int lane = threadIdx.x & 31, wid = threadIdx.x >> 5;
    if (lane == 0) sh[wid] = v;
    __syncthreads();
    float r = sh[0] + sh[1] + sh[2] + sh[3];
    __syncthreads();
    return r;
}

__global__ __launch_bounds__(128) void k_fuse(const float* __restrict__ attn,
                                              const float* __restrict__ fc_w,
                                              const float* __restrict__ fc_b,
                                              float* __restrict__ out) {
    __shared__ float sh[4];
    int b = blockIdx.x, d = threadIdx.x;
    float v0 = g_outs[((size_t)0 * BB + b) * D + d];
    float v1 = g_outs[((size_t)1 * BB + b) * D + d];
    float v2 = g_outs[((size_t)2 * BB + b) * D + d];
    float a  = attn[d];
    float s0 = blk_red(v0 * a, sh);
    float s1 = blk_red(v1 * a, sh);
    float s2 = blk_red(v2 * a, sh);
    s0 = tanhf(s0); s1 = tanhf(s1); s2 = tanhf(s2);
    float mx = fmaxf(s0, fmaxf(s1, s2));
    float e0 = expf(s0 - mx), e1 = expf(s1 - mx), e2 = expf(s2 - mx);
    float inv = 1.f / (e0 + e1 + e2);
    float emb = (e0 * v0 + e1 * v1 + e2 * v2) * inv;
    float n2  = blk_red(emb * emb, sh);
    float nrm = sqrtf(n2);
    emb = emb / fmaxf(nrm, 1e-12f);
    #pragma unroll
    for (int nc = 0; nc < NC; nc++) {
        float r = blk_red(emb * fc_w[d * NC + nc], sh);
        if (d == 0) out[b * NC + nc] = r + fc_b[nc];
    }
}

// ---------------- launch ----------------
extern "C" void kernel_launch(void* const* d_in, const int* in_sizes, int n_in,
                              void* d_out, int out_size) {
    (void)in_sizes; (void)n_in; (void)out_size;
    const int*   ids       = (const int*)  d_in[0];
    const float* feats     = (const float*)d_in[1];
    const float* edge_emb  = (const float*)d_in[2];
    const int*   adj_nodes = (const int*)  d_in[3];
    const int*   adj_edges = (const int*)  d_in[4];
    const float* W_self    = (const float*)d_in[5];
    const float* W_neigh   = (const float*)d_in[6];
    const float* W_edge    = (const float*)d_in[7];
    const float* attn      = (const float*)d_in[8];
    const float* fc_w      = (const float*)d_in[9];
    const float* fc_b      = (const float*)d_in[10];
    float* out = (float*)d_out;

    k_idx<<<(NMP * M1 + 255) / 256, 256>>>(ids, adj_nodes, adj_edges);
    k_mean_hop2<<<NMP * M1 / 8, 256>>>(feats, edge_emb, adj_nodes, adj_edges);
    k_mean_hop1<<<NMP * BB / 8, 256>>>(feats, edge_emb);
    gemm_h<0><<<dim3(M1 / 64, NMP), 256>>>(feats, ids, W_self, W_neigh, 0);
    gemm_h<1><<<dim3(BB / 64, NMP), 256>>>(feats, ids, W_self, W_neigh, 0);
    gemm_edge<<<dim3(M1 / 64, NMP), 128>>>(edge_emb, W_edge, 0);
    k_mean_L1<<<NMP * BB / 8, 256>>>();
    gemm_h<2><<<dim3(BB / 64, NMP), 256>>>(feats, ids, W_self, W_neigh, 1);
    k_fuse<<<BB, 128>>>(attn, fc_w, fc_b, out);
}

// round 2
// speedup vs baseline: 1.9204x; 1.9204x over previous
#include <cuda_runtime.h>
#include <cstdint>

#define NMP     3
#define NNODES  50000
#define D       128
#define E       32
#define DEG     32
#define NEDGE   200000
#define BB      1024
#define S       16
#define NC      8
#define M1      (BB*S)      /* 16384 */
#define DE      (D+E)       /* 160 */

// ---------------- scratch (static device globals; no runtime alloc) ----------------
__device__ int   g_nb1 [NMP*M1];
__device__ int   g_eid1[NMP*M1];
__device__ float g_nin2[(size_t)NMP*M1*DE];   // hop-2 mean [3,16384,160]
__device__ float g_nin1[NMP*BB*DE];           // hop-1 mean [3,1024,160]
__device__ float g_h1  [(size_t)NMP*M1*D];    // layer0 feats at hop-1 [3,16384,128]
__device__ float g_h0  [NMP*BB*D];            // layer0 feats at root  [3,1024,128]
__device__ float g_e1  [(size_t)NMP*M1*E];    // layer0 updated edges  [3,16384,32]
__device__ float g_ninL1[NMP*BB*DE];          // layer1 mean [3,1024,160]
__device__ float g_outs[NMP*BB*D];            // per-metapath embedding [3,1024,128]

// ---------------- helpers ----------------
__device__ __forceinline__ float tf32r(float x) {
    uint32_t u; asm("cvt.rna.tf32.f32 %0, %1;" : "=r"(u) : "f"(x));
    return __uint_as_float(u);
}
__device__ __forceinline__ uint32_t fu(float x) { return __float_as_uint(x); }

#define MMA_TF32(c, a, b) \
    asm volatile("mma.sync.aligned.m16n8k8.row.col.f32.tf32.tf32.f32 " \
        "{%0,%1,%2,%3}, {%4,%5,%6,%7}, {%8,%9}, {%0,%1,%2,%3};" \
        : "+f"((c)[0]), "+f"((c)[1]), "+f"((c)[2]), "+f"((c)[3]) \
        : "r"((a)[0]), "r"((a)[1]), "r"((a)[2]), "r"((a)[3]), \
          "r"((b)[0]), "r"((b)[1]))

// ---------------- 1) hop-1 neighbor / edge ids ----------------
__global__ void k_idx(const int* __restrict__ ids,
                      const int* __restrict__ adj_nodes,
                      const int* __restrict__ adj_edges) {
    int t = blockIdx.x * blockDim.x + threadIdx.x;
    if (t >= NMP * M1) return;
    int mp = t / M1;
    int r  = t % M1;
    int b  = r >> 4;
    int s  = r & 15;
    long base = ((long)mp * NNODES + ids[b]) * DEG + s;
    g_nb1[t]  = adj_nodes[base];
    g_eid1[t] = adj_edges[base];
}

// ---------------- 2) hop-2 gather + mean -> nin2 ----------------
__global__ void k_mean_hop2(const float* __restrict__ feats,
                            const float* __restrict__ edge_emb,
                            const int* __restrict__ adj_nodes,
                            const int* __restrict__ adj_edges) {
    int w    = (blockIdx.x * blockDim.x + threadIdx.x) >> 5;
    int lane = threadIdx.x & 31;
    if (w >= NMP * M1) return;
    int mp = w / M1;
    long abase = ((long)mp * NNODES + g_nb1[w]) * DEG;
    const int* an = adj_nodes + abase;
    const int* ae = adj_edges + abase;
    float4 aF = make_float4(0.f,0.f,0.f,0.f);
    float4 aE = make_float4(0.f,0.f,0.f,0.f);
    #pragma unroll
    for (int s = 0; s < S; s++) {
        int nb = an[s];
        float4 v = ((const float4*)(feats + (long)nb * D))[lane];
        aF.x += v.x; aF.y += v.y; aF.z += v.z; aF.w += v.w;
        if (lane < E/4) {
            int e = ae[s];
            float4 u = ((const float4*)(edge_emb + ((long)mp * NEDGE + e) * E))[lane];
            aE.x += u.x; aE.y += u.y; aE.z += u.z; aE.w += u.w;
        }
    }
    const float inv = 1.0f / S;
    float4* o = (float4*)(g_nin2 + (size_t)w * DE);
    o[lane] = make_float4(aF.x*inv, aF.y*inv, aF.z*inv, aF.w*inv);
    if (lane < E/4)
        o[D/4 + lane] = make_float4(aE.x*inv, aE.y*inv, aE.z*inv, aE.w*inv);
}

// ---------------- 3) hop-1 gather + mean -> nin1 ----------------
__global__ void k_mean_hop1(const float* __restrict__ feats,
                            const float* __restrict__ edge_emb) {
    int w    = (blockIdx.x * blockDim.x + threadIdx.x) >> 5;
    int lane = threadIdx.x & 31;
    if (w >= NMP * BB) return;
    int mp = w / BB;
    int b  = w % BB;
    int base = mp * M1 + b * S;
    float4 aF = make_float4(0.f,0.f,0.f,0.f);
    float4 aE = make_float4(0.f,0.f,0.f,0.f);
    #pragma unroll
    for (int s = 0; s < S; s++) {
        int nb = g_nb1[base + s];
        float4 v = ((const float4*)(feats + (long)nb * D))[lane];
        aF.x += v.x; aF.y += v.y; aF.z += v.z; aF.w += v.w;
        if (lane < E/4) {
            int e = g_eid1[base + s];
            float4 u = ((const float4*)(edge_emb + ((long)mp * NEDGE + e) * E))[lane];
            aE.x += u.x; aE.y += u.y; aE.z += u.z; aE.w += u.w;
        }
    }
    const float inv = 1.0f / S;
    float4* o = (float4*)(g_nin1 + (size_t)w * DE);
    o[lane] = make_float4(aF.x*inv, aF.y*inv, aF.z*inv, aF.w*inv);
    if (lane < E/4)
        o[D/4 + lane] = make_float4(aE.x*inv, aE.y*inv, aE.z*inv, aE.w*inv);
}

// ---------------- layer-1 mean over (h1 || e1) -> ninL1 ----------------
__global__ void k_mean_L1() {
    int w    = (blockIdx.x * blockDim.x + threadIdx.x) >> 5;
    int lane = threadIdx.x & 31;
    if (w >= NMP * BB) return;
    int mp = w / BB;
    int b  = w % BB;
    size_t base = (size_t)mp * M1 + (size_t)b * S;
    float4 aF = make_float4(0.f,0.f,0.f,0.f);
    float4 aE = make_float4(0.f,0.f,0.f,0.f);
    #pragma unroll
    for (int s = 0; s < S; s++) {
        float4 v = ((const float4*)(g_h1 + (base + s) * D))[lane];
        aF.x += v.x; aF.y += v.y; aF.z += v.z; aF.w += v.w;
        if (lane < E/4) {
            float4 u = ((const float4*)(g_e1 + (base + s) * E))[lane];
            aE.x += u.x; aE.y += u.y; aE.z += u.z; aE.w += u.w;
        }
    }
    const float inv = 1.0f / S;
    float4* o = (float4*)(g_ninL1 + (size_t)w * DE);
    o[lane] = make_float4(aF.x*inv, aF.y*inv, aF.z*inv, aF.w*inv);
    if (lane < E/4)
        o[D/4 + lane] = make_float4(aE.x*inv, aE.y*inv, aE.z*inv, aE.w*inv);
}

// ---------------- node GEMM (TF32 tensor core) ----------------
// out = relu(P1row @ Wself + P2row @ Wneigh), K = 128 + 160 = 288
// MODE 0: h1  (M=16384, P1 = feats[g_nb1], P2 = nin2)
// MODE 1: h0  (M=1024,  P1 = feats[ids],  P2 = nin1)
// MODE 2: outs(M=1024,  P1 = g_h0 direct, P2 = ninL1)
template<int MODE>
__global__ __launch_bounds__(256) void gemm_h(const float* __restrict__ feats,
                                              const int*   __restrict__ ids,
                                              const float* __restrict__ W_self,
                                              const float* __restrict__ W_neigh,
                                              int l) {
    constexpr int M    = (MODE == 0) ? M1 : BB;
    constexpr int KTOT = D + DE;          // 288
    constexpr int NSTG = KTOT / 16;       // 18
    int mp = blockIdx.y;
    int m0 = blockIdx.x * 128;

    __shared__ float As[2][128][20];      // [buf][m][k], pad->conflict-free frags
    __shared__ float Bs[2][16][136];      // [buf][k][n], pad 8 -> conflict-free
    __shared__ const float* rowp[128];

    int tid  = threadIdx.x;
    int lane = tid & 31;
    int w    = tid >> 5;
    int wm   = w >> 2;          // 0..1   (rows 64*wm)
    int wn   = w & 3;           // 0..3   (cols 32*wn)
    int ar   = tid >> 1;        // A ld: row 0..127
    int kq   = (tid & 1) * 8;   // A ld: k offset 0/8
    int bk   = tid >> 4;        // B ld: k row 0..15
    int bn   = (tid & 15) * 8;  // B ld: n offset

    const float* P2; float* Out;
    if (MODE == 0)      { P2 = g_nin2;  Out = g_h1;   }
    else if (MODE == 1) { P2 = g_nin1;  Out = g_h0;   }
    else                { P2 = g_ninL1; Out = g_outs; }

    if (tid < 128) {
        int m = m0 + tid;
        const float* p;
        if (MODE == 0)      p = feats + (long)g_nb1[mp * M1 + m] * D;
        else if (MODE == 1) p = feats + (long)ids[m] * D;
        else                p = g_h0 + ((long)mp * BB + m) * D;
        rowp[tid] = p;
    }
    __syncthreads();

    const float* Wsp = W_self  + ((long)(mp * 2 + l)) * D  * D;
    const float* Wnp = W_neigh + ((long)(mp * 2 + l)) * DE * D;
    const float* P2p = P2 + ((size_t)mp * M + m0) * DE;

    float acc[4][4][4];
    #pragma unroll
    for (int i = 0; i < 4; i++)
        #pragma unroll
        for (int j = 0; j < 4; j++)
            #pragma unroll
            for (int q = 0; q < 4; q++) acc[i][j][q] = 0.f;

    float4 ra0, ra1, rb0, rb1;

#define LDG_H(K0) do {                                                          \
    int _k = (K0);                                                              \
    const float* ap = (_k < D) ? rowp[ar] + _k                                  \
                               : P2p + (long)ar * DE + (_k - D);                \
    ra0 = *(const float4*)(ap + kq);                                            \
    ra1 = *(const float4*)(ap + kq + 4);                                        \
    const float* wrow = (_k < D) ? (Wsp + (long)(_k + bk) * D)                  \
                                 : (Wnp + (long)(_k - D + bk) * D);             \
    rb0 = *(const float4*)(wrow + bn);                                          \
    rb1 = *(const float4*)(wrow + bn + 4);                                      \
} while (0)

#define STS_H(BUF) do {                                                         \
    As[BUF][ar][kq+0] = tf32r(ra0.x); As[BUF][ar][kq+1] = tf32r(ra0.y);         \
    As[BUF][ar][kq+2] = tf32r(ra0.z); As[BUF][ar][kq+3] = tf32r(ra0.w);         \
    As[BUF][ar][kq+4] = tf32r(ra1.x); As[BUF][ar][kq+5] = tf32r(ra1.y);         \
    As[BUF][ar][kq+6] = tf32r(ra1.z); As[BUF][ar][kq+7] = tf32r(ra1.w);         \
    Bs[BUF][bk][bn+0] = tf32r(rb0.x); Bs[BUF][bk][bn+1] = tf32r(rb0.y);         \
    Bs[BUF][bk][bn+2] = tf32r(rb0.z); Bs[BUF][bk][bn+3] = tf32r(rb0.w);         \
    Bs[BUF][bk][bn+4] = tf32r(rb1.x); Bs[BUF][bk][bn+5] = tf32r(rb1.y);         \
    Bs[BUF][bk][bn+6] = tf32r(rb1.z); Bs[BUF][bk][bn+7] = tf32r(rb1.w);         \
} while (0)

    LDG_H(0);
    STS_H(0);
    __syncthreads();

    for (int it = 0; it < NSTG; ++it) {
        int cur = it & 1;
        if (it + 1 < NSTG) LDG_H((it + 1) * 16);

        #pragma unroll
        for (int kk = 0; kk < 16; kk += 8) {
            uint32_t afr[4][4], bfr[4][2];
            #pragma unroll
            for (int mt = 0; mt < 4; mt++) {
                int r = wm * 64 + mt * 16 + (lane >> 2);
                int c = kk + (lane & 3);
                afr[mt][0] = fu(As[cur][r    ][c    ]);
                afr[mt][1] = fu(As[cur][r + 8][c    ]);
                afr[mt][2] = fu(As[cur][r    ][c + 4]);
                afr[mt][3] = fu(As[cur][r + 8][c + 4]);
            }
            #pragma unroll
            for (int nt = 0; nt < 4; nt++) {
                int cN = wn * 32 + nt * 8 + (lane >> 2);
                bfr[nt][0] = fu(Bs[cur][kk     + (lane & 3)][cN]);
                bfr[nt][1] = fu(Bs[cur][kk + 4 + (lane & 3)][cN]);
            }
            #pragma unroll
            for (int mt = 0; mt < 4; mt++)
                #pragma unroll
                for (int nt = 0; nt < 4; nt++)
                    MMA_TF32(acc[mt][nt], afr[mt], bfr[nt]);
        }

        if (it + 1 < NSTG) { STS_H(cur ^ 1); __syncthreads(); }
    }
#undef LDG_H
#undef STS_H

    size_t ob = ((size_t)mp * M + m0) * D;
    #pragma unroll
    for (int mt = 0; mt < 4; mt++) {
        int r = wm * 64 + mt * 16 + (lane >> 2);
        #pragma unroll
        for (int nt = 0; nt < 4; nt++) {
            int c = wn * 32 + nt * 8 + 2 * (lane & 3);
            float2 v0, v1;
            v0.x = fmaxf(acc[mt][nt][0], 0.f);
            v0.y = fmaxf(acc[mt][nt][1], 0.f);
            v1.x = fmaxf(acc[mt][nt][2], 0.f);
            v1.y = fmaxf(acc[mt][nt][3], 0.f);
            *(float2*)(Out + ob + (size_t)r       * D + c) = v0;
            *(float2*)(Out + ob + (size_t)(r + 8) * D + c) = v1;
        }
    }
}

// ---------------- edge GEMM (TF32): e1 = relu([h0_rep || h1 || ee1] @ W_edge) ----------------
__global__ __launch_bounds__(256) void gemm_edge(const float* __restrict__ edge_emb,
                                                 const float* __restrict__ W_edge,
                                                 int l) {
    constexpr int KTOT = 2 * D + E;       // 288
    constexpr int NSTG = KTOT / 16;       // 18
    int mp = blockIdx.y;
    int m0 = blockIdx.x * 128;

    __shared__ float As[2][128][20];
    __shared__ float Bs[2][16][40];
    __shared__ const float* pH0s[128];
    __shared__ const float* pH1s[128];
    __shared__ const float* pEs[128];

    int tid  = threadIdx.x;
    int lane = tid & 31;
    int w    = tid >> 5;          // warp 0..7, rows 16*w
    int ar   = tid >> 1;
    int kq   = (tid & 1) * 8;

    if (tid < 128) {
        int m = m0 + tid;
        pH0s[tid] = g_h0 + ((long)mp * BB + (m >> 4)) * D;
        pH1s[tid] = g_h1 + ((size_t)mp * M1 + m) * D;
        pEs[tid]  = edge_emb + ((long)mp * NEDGE + g_eid1[mp * M1 + m]) * E;
    }
    __syncthreads();

    const float* Wep = W_edge + ((long)(mp * 2 + l)) * KTOT * E;

    float acc[4][4];
    #pragma unroll
    for (int i = 0; i < 4; i++)
        #pragma unroll
        for (int q = 0; q < 4; q++) acc[i][q] = 0.f;

    float4 ra0, ra1, rb;

#define LDG_E(K0) do {                                                          \
    int _k = (K0);                                                              \
    const float* ap;                                                            \
    if (_k < D)            ap = pH0s[ar] + _k;                                  \
    else if (_k < 2 * D)   ap = pH1s[ar] + (_k - D);                            \
    else                   ap = pEs[ar]  + (_k - 2 * D);                        \
    ra0 = *(const float4*)(ap + kq);                                            \
    ra1 = *(const float4*)(ap + kq + 4);                                        \
    if (tid < 128)                                                              \
        rb = *(const float4*)(Wep + (long)(_k + (tid >> 3)) * E + (tid & 7) * 4);\
} while (0)

#define STS_E(BUF) do {                                                         \
    As[BUF][ar][kq+0] = tf32r(ra0.x); As[BUF][ar][kq+1] = tf32r(ra0.y);         \
    As[BUF][ar][kq+2] = tf32r(ra0.z); As[BUF][ar][kq+3] = tf32r(ra0.w);         \
    As[BUF][ar][kq+4] = tf32r(ra1.x); As[BUF][ar][kq+5] = tf32r(ra1.y);         \
    As[BUF][ar][kq+6] = tf32r(ra1.z); As[BUF][ar][kq+7] = tf32r(ra1.w);         \
    if (tid < 128) {                                                            \
        int _bk = tid >> 3, _bn = (tid & 7) * 4;                                \
        Bs[BUF][_bk][_bn+0] = tf32r(rb.x); Bs[BUF][_bk][_bn+1] = tf32r(rb.y);   \
        Bs[BUF][_bk][_bn+2] = tf32r(rb.z); Bs[BUF][_bk][_bn+3] = tf32r(rb.w);   \
    }                                                                           \
} while (0)

    LDG_E(0);
    STS_E(0);
    __syncthreads();

    for (int it = 0; it < NSTG; ++it) {
        int cur = it & 1;
        if (it + 1 < NSTG) LDG_E((it + 1) * 16);

        #pragma unroll
        for (int kk = 0; kk < 16; kk += 8) {
            uint32_t afr[4], bfr[4][2];
            int r = w * 16 + (lane >> 2);
            int c = kk + (lane & 3);
            afr[0] = fu(As[cur][r    ][c    ]);
            afr[1] = fu(As[cur][r + 8][c    ]);
            afr[2] = fu(As[cur][r    ][c + 4]);
            afr[3] = fu(As[cur][r + 8][c + 4]);
            #pragma unroll
            for (int nt = 0; nt < 4; nt++) {
                int cN = nt * 8 + (lane >> 2);
                bfr[nt][0] = fu(Bs[cur][kk     + (lane & 3)][cN]);
                bfr[nt][1] = fu(Bs[cur][kk + 4 + (lane & 3)][cN]);
            }
            #pragma unroll
            for (int nt = 0; nt < 4; nt++)
                MMA_TF32(acc[nt], afr, bfr[nt]);
        }

        if (it + 1 < NSTG) { STS_E(cur ^ 1); __syncthreads(); }
    }
#undef LDG_E
#undef STS_E

    size_t ob = ((size_t)mp * M1 + m0) * E;
    int r = w * 16 + (lane >> 2);
    #pragma unroll
    for (int nt = 0; nt < 4; nt++) {
        int c = nt * 8 + 2 * (lane & 3);
        float2 v0, v1;
        v0.x = fmaxf(acc[nt][0], 0.f);
        v0.y = fmaxf(acc[nt][1], 0.f);
        v1.x = fmaxf(acc[nt][2], 0.f);
        v1.y = fmaxf(acc[nt][3], 0.f);
        *(float2*)(g_e1 + ob + (size_t)r       * E + c) = v0;
        *(float2*)(g_e1 + ob + (size_t)(r + 8) * E + c) = v1;
    }
}

// ---------------- final fuse: attention + normalize + fc ----------------
__device__ __forceinline__ float blk_red(float v, float* sh) {
    #pragma unroll
    for (int o = 16; o; o >>= 1) v += __shfl_xor_sync(0xffffffffu, v, o);
    int lane = threadIdx.x & 31, wid = threadIdx.x >> 5;
    if (lane == 0) sh[wid] = v;
    __syncthreads();
    float r = sh[0] + sh[1] + sh[2] + sh[3];
    __syncthreads();
    return r;
}

__global__ __launch_bounds__(128) void k_fuse(const float* __restrict__ attn,
                                              const float* __restrict__ fc_w,
                                              const float* __restrict__ fc_b,
                                              float* __restrict__ out) {
    __shared__ float sh[4];
    int b = blockIdx.x, d = threadIdx.x;
    float v0 = g_outs[((size_t)0 * BB + b) * D + d];
    float v1 = g_outs[((size_t)1 * BB + b) * D + d];
    float v2 = g_outs[((size_t)2 * BB + b) * D + d];
    float a  = attn[d];
    float s0 = blk_red(v0 * a, sh);
    float s1 = blk_red(v1 * a, sh);
    float s2 = blk_red(v2 * a, sh);
    s0 = tanhf(s0); s1 = tanhf(s1); s2 = tanhf(s2);
    float mx = fmaxf(s0, fmaxf(s1, s2));
    float e0 = expf(s0 - mx), e1 = expf(s1 - mx), e2 = expf(s2 - mx);
    float inv = 1.f / (e0 + e1 + e2);
    float emb = (e0 * v0 + e1 * v1 + e2 * v2) * inv;
    float n2  = blk_red(emb * emb, sh);
    float nrm = sqrtf(n2);
    emb = emb / fmaxf(nrm, 1e-12f);
    #pragma unroll
    for (int nc = 0; nc < NC; nc++) {
        float r = blk_red(emb * fc_w[d * NC + nc], sh);
        if (d == 0) out[b * NC + nc] = r + fc_b[nc];
    }
}

// ---------------- launch ----------------
extern "C" void kernel_launch(void* const* d_in, const int* in_sizes, int n_in,
                              void* d_out, int out_size) {
    (void)in_sizes; (void)n_in; (void)out_size;
    const int*   ids       = (const int*)  d_in[0];
    const float* feats     = (const float*)d_in[1];
    const float* edge_emb  = (const float*)d_in[2];
    const int*   adj_nodes = (const int*)  d_in[3];
    const int*   adj_edges = (const int*)  d_in[4];
    const float* W_self    = (const float*)d_in[5];
    const float* W_neigh   = (const float*)d_in[6];
    const float* W_edge    = (const float*)d_in[7];
    const float* attn      = (const float*)d_in[8];
    const float* fc_w      = (const float*)d_in[9];
    const float* fc_b      = (const float*)d_in[10];
    float* out = (float*)d_out;

    k_idx<<<(NMP * M1 + 255) / 256, 256>>>(ids, adj_nodes, adj_edges);
    k_mean_hop2<<<NMP * M1 / 8, 256>>>(feats, edge_emb, adj_nodes, adj_edges);
    k_mean_hop1<<<NMP * BB / 8, 256>>>(feats, edge_emb);
    gemm_h<0><<<dim3(M1 / 128, NMP), 256>>>(feats, ids, W_self, W_neigh, 0);
    gemm_h<1><<<dim3(BB / 128, NMP), 256>>>(feats, ids, W_self, W_neigh, 0);
    gemm_edge<<<dim3(M1 / 128, NMP), 256>>>(edge_emb, W_edge, 0);
    k_mean_L1<<<NMP * BB / 8, 256>>>();
    gemm_h<2><<<dim3(BB / 128, NMP), 256>>>(feats, ids, W_self, W_neigh, 1);
    k_fuse<<<BB, 128>>>(attn, fc_w, fc_b, out);
}